// round 1
// baseline (speedup 1.0000x reference)
#include <cuda_runtime.h>

#define NPTS    8192
#define NCODES  16384
#define DIM     64

// output layout (floats)
#define OFF_ZQ     0
#define OFF_LOSS   524288
#define OFF_IDX    524289
#define OFF_NUNIQ  532481
#define OFF_USAGE  532482
#define OFF_TOTAL  548866

__device__ int    g_idx[NPTS];
__device__ float  g_b[NCODES];
__device__ double g_loss;

// ---------------------------------------------------------------------------
// 0) init: zero usage region in d_out, zero loss accumulator
// ---------------------------------------------------------------------------
__global__ void vq_init(float* out) {
    int t = blockIdx.x * blockDim.x + threadIdx.x;
    if (t < NCODES) out[OFF_USAGE + t] = 0.0f;
    if (t == 0) g_loss = 0.0;
}

// ---------------------------------------------------------------------------
// 1) b_k = sum_d e[k][d]^2  (sequential over d)
// ---------------------------------------------------------------------------
__global__ void vq_codenorm(const float* __restrict__ emb) {
    int k = blockIdx.x * blockDim.x + threadIdx.x;
    if (k >= NCODES) return;
    const float* row = emb + (size_t)k * DIM;
    float s = 0.0f;
#pragma unroll 8
    for (int d = 0; d < DIM; ++d) s = fmaf(row[d], row[d], s);
    g_b[k] = s;
}

// ---------------------------------------------------------------------------
// 2) main argmin kernel.
//    Block: 256 threads, 64 points x all 16384 codes (tiles of 256 codes).
//    Register tile: 8 points x 8 codes per thread.
//    smem: es (transposed e tile, 64 x 257), zs (64 x 65), sa (64), sb (256)
// ---------------------------------------------------------------------------
#define ES_FLOATS (64 * 257)
#define ZS_FLOATS (64 * 65)
#define SM_FLOATS (ES_FLOATS + ZS_FLOATS + 64 + 256)

__global__ __launch_bounds__(256, 1)
void vq_argmin(const float* __restrict__ z, const float* __restrict__ emb,
               float* __restrict__ out) {
    extern __shared__ float smem[];
    float* es = smem;                 // [d][code] stride 257
    float* zs = smem + ES_FLOATS;     // [p][d]    stride 65
    float* sa = zs + ZS_FLOATS;       // [64]
    float* sb = sa + 64;              // [256]

    const int tid = threadIdx.x;
    const int pg  = tid >> 5;         // point group 0..7  (8 pts each)
    const int cg  = tid & 31;         // code lane 0..31 (codes cg + j*32)

    const int pbase   = blockIdx.x * 64;     // 64 points per block
    const int bb      = pbase >> 10;         // batch index (same for whole block)
    const int posbase = pbase & 1023;        // h*32+w base

    // stage z tile (transpose from [b][d][pos] to zs[p][d]); coalesced reads
    for (int t = tid; t < 64 * 64; t += 256) {
        int d   = t >> 6;
        int pos = t & 63;
        float v = z[(size_t)bb * 65536 + (size_t)d * 1024 + posbase + pos];
        zs[pos * 65 + d] = v;
    }
    __syncthreads();

    // a_p = sum_d fl(z^2), strictly sequential d = 0..63 (match jnp.sum order)
    if (tid < 64) {
        float s = 0.0f;
        const float* zr = zs + tid * 65;
        for (int d = 0; d < DIM; ++d) {
            float q = __fmul_rn(zr[d], zr[d]);
            s = __fadd_rn(s, q);
        }
        sa[tid] = s;
    }
    __syncthreads();

    float a_r[8];
#pragma unroll
    for (int i = 0; i < 8; ++i) a_r[i] = sa[pg * 8 + i];

    float bestd[8];
    int   bestk[8];
#pragma unroll
    for (int i = 0; i < 8; ++i) { bestd[i] = __int_as_float(0x7f800000); bestk[i] = 0; }

    for (int tile = 0; tile < NCODES / 256; ++tile) {
        const int kbase = tile * 256;
        __syncthreads();  // protect es/sb from previous iteration's readers
        // stage e tile transposed: es[d][code_local], coalesced global reads
        for (int t = tid; t < 256 * 64; t += 256) {
            int cl = t >> 6;
            int d  = t & 63;
            es[d * 257 + cl] = emb[(size_t)(kbase + cl) * DIM + d];
        }
        sb[tid] = g_b[kbase + tid];
        __syncthreads();

        float acc[8][8];
#pragma unroll
        for (int i = 0; i < 8; ++i)
#pragma unroll
            for (int j = 0; j < 8; ++j) acc[i][j] = 0.0f;

#pragma unroll 4
        for (int d = 0; d < DIM; ++d) {
            float zv[8], ev[8];
#pragma unroll
            for (int i = 0; i < 8; ++i) zv[i] = zs[(pg * 8 + i) * 65 + d];
#pragma unroll
            for (int j = 0; j < 8; ++j) ev[j] = es[d * 257 + cg + j * 32];
#pragma unroll
            for (int i = 0; i < 8; ++i)
#pragma unroll
                for (int j = 0; j < 8; ++j)
                    acc[i][j] = fmaf(zv[i], ev[j], acc[i][j]);
        }

        // compare: d = fl( fl(a + b) - 2*c ) ; ties -> smaller index
#pragma unroll
        for (int j = 0; j < 8; ++j) {
            int   k  = kbase + cg + j * 32;
            float bk = sb[cg + j * 32];
#pragma unroll
            for (int i = 0; i < 8; ++i) {
                float t1   = __fadd_rn(a_r[i], bk);
                float dist = fmaf(-2.0f, acc[i][j], t1);
                if (dist < bestd[i] || (dist == bestd[i] && k < bestk[i])) {
                    bestd[i] = dist;
                    bestk[i] = k;
                }
            }
        }
    }

    // cross-thread reduction over the 32 code lanes per point group
    __syncthreads();
    float* rd = smem;                         // 256*8 floats
    int*   ri = (int*)(smem + 2048);          // 256*8 ints
#pragma unroll
    for (int i = 0; i < 8; ++i) {
        rd[tid * 8 + i] = bestd[i];
        ri[tid * 8 + i] = bestk[i];
    }
    __syncthreads();

    if (tid < 64) {
        int p  = tid;
        int mg = p >> 3;    // which point group
        int mi = p & 7;     // which point within group
        float bd = __int_as_float(0x7f800000);
        int   bk = 0x7fffffff;
        for (int c = 0; c < 32; ++c) {
            int t2   = (mg * 32 + c) * 8 + mi;
            float d2 = rd[t2];
            int   k2 = ri[t2];
            if (d2 < bd || (d2 == bd && k2 < bk)) { bd = d2; bk = k2; }
        }
        g_idx[pbase + p] = bk;
        out[OFF_IDX + pbase + p] = (float)bk;
    }
}

// ---------------------------------------------------------------------------
// 3) usage scatter (idempotent stores)
// ---------------------------------------------------------------------------
__global__ void vq_scatter(float* out) {
    int n = blockIdx.x * blockDim.x + threadIdx.x;
    if (n >= NPTS) return;
    out[OFF_USAGE + g_idx[n]] = 1.0f;
}

// ---------------------------------------------------------------------------
// 4) z_q gather (b,c,h,w layout == input layout) + loss accumulation
// ---------------------------------------------------------------------------
__global__ void vq_zq_loss(const float* __restrict__ z,
                           const float* __restrict__ emb,
                           float* __restrict__ out) {
    __shared__ double sd[256];
    int g = blockIdx.x * blockDim.x + threadIdx.x;  // < 524288
    int d   = (g >> 10) & 63;
    int bb  = g >> 16;
    int pos = g & 1023;
    int n   = bb * 1024 + pos;
    int k   = g_idx[n];
    float e  = emb[(size_t)k * DIM + d];
    float zv = z[g];
    out[OFF_ZQ + g] = e;
    float diff = e - zv;
    sd[threadIdx.x] = (double)diff * (double)diff;
    __syncthreads();
    for (int s = 128; s > 0; s >>= 1) {
        if (threadIdx.x < s) sd[threadIdx.x] += sd[threadIdx.x + s];
        __syncthreads();
    }
    if (threadIdx.x == 0) atomicAdd(&g_loss, sd[0]);
}

// ---------------------------------------------------------------------------
// 5) finalize: num_unique, total_usage, loss
// ---------------------------------------------------------------------------
__global__ void vq_finalize(float* out) {
    __shared__ float sf[512];
    float s = 0.0f;
    for (int t = threadIdx.x; t < NCODES; t += 512) s += out[OFF_USAGE + t];
    sf[threadIdx.x] = s;
    __syncthreads();
    for (int st = 256; st > 0; st >>= 1) {
        if (threadIdx.x < st) sf[threadIdx.x] += sf[threadIdx.x + st];
        __syncthreads();
    }
    if (threadIdx.x == 0) {
        float total = sf[0];                       // exact integer-valued sum
        out[OFF_NUNIQ] = total;
        out[OFF_TOTAL] = total / (float)NCODES;
        float m = (float)(g_loss / 524288.0);      // mean squared diff
        out[OFF_LOSS] = m + 0.25f * m;             // (1 + beta) * mean
    }
}

// ---------------------------------------------------------------------------
extern "C" void kernel_launch(void* const* d_in, const int* in_sizes, int n_in,
                              void* d_out, int out_size) {
    const float* z;
    const float* emb;
    if (in_sizes[0] == NPTS * DIM * /*B*/ 1 * 64 || in_sizes[0] == 524288) {
        z = (const float*)d_in[0];
        emb = (const float*)d_in[1];
    } else {
        z = (const float*)d_in[1];
        emb = (const float*)d_in[0];
    }
    float* out = (float*)d_out;

    static int attr_set = 0;
    if (!attr_set) {
        cudaFuncSetAttribute(vq_argmin, cudaFuncAttributeMaxDynamicSharedMemorySize,
                             SM_FLOATS * (int)sizeof(float));
        attr_set = 1;
    }

    vq_init<<<(NCODES + 255) / 256, 256>>>(out);
    vq_codenorm<<<(NCODES + 255) / 256, 256>>>(emb);
    vq_argmin<<<NPTS / 64, 256, SM_FLOATS * sizeof(float)>>>(z, emb, out);
    vq_scatter<<<(NPTS + 255) / 256, 256>>>(out);
    vq_zq_loss<<<524288 / 256, 256>>>(z, emb, out);
    vq_finalize<<<1, 512>>>(out);
}

// round 2
// speedup vs baseline: 1.5281x; 1.5281x over previous
#include <cuda_runtime.h>

#define NPTS    8192
#define NCODES  16384
#define DIM     64

// output layout (floats)
#define OFF_ZQ     0
#define OFF_LOSS   524288
#define OFF_IDX    524289
#define OFF_NUNIQ  532481
#define OFF_USAGE  532482
#define OFF_TOTAL  548866

__device__ int    g_idx[NPTS];
__device__ float  g_b[NCODES];
__device__ float  g_eT[DIM * NCODES];   // transposed codebook [d][k]
__device__ double g_loss;

// ---------------------------------------------------------------------------
// packed f32x2 helpers
// ---------------------------------------------------------------------------
#define PACK_DUP(dst, f) \
    asm("mov.b64 %0, {%1, %1};" : "=l"(dst) : "f"(f))
#define FMA2(acc, a, b) \
    asm("fma.rn.f32x2 %0, %1, %2, %0;" : "+l"(acc) : "l"(a), "l"(b))
#define UNPACK2(lo, hi, v) \
    asm("mov.b64 {%0, %1}, %2;" : "=f"(lo), "=f"(hi) : "l"(v))

__device__ __forceinline__ void cp_async16(void* smem_dst, const void* gmem_src) {
    unsigned s = (unsigned)__cvta_generic_to_shared(smem_dst);
    asm volatile("cp.async.cg.shared.global [%0], [%1], 16;" :: "r"(s), "l"(gmem_src));
}
__device__ __forceinline__ void cp_commit() {
    asm volatile("cp.async.commit_group;");
}
__device__ __forceinline__ void cp_wait1() {
    asm volatile("cp.async.wait_group 1;");
}

// ---------------------------------------------------------------------------
// 0) init: zero usage region in d_out, zero loss accumulator
// ---------------------------------------------------------------------------
__global__ void vq_init(float* out) {
    int t = blockIdx.x * blockDim.x + threadIdx.x;
    if (t < NCODES) out[OFF_USAGE + t] = 0.0f;
    if (t == 0) g_loss = 0.0;
}

// ---------------------------------------------------------------------------
// 1) transpose codebook [k][d] -> g_eT [d][k] (smem-tiled)
// ---------------------------------------------------------------------------
__global__ void vq_transpose(const float* __restrict__ emb) {
    __shared__ float t[32][33];
    int kb = blockIdx.x * 32;
    int db = blockIdx.y * 32;
    int x = threadIdx.x, y = threadIdx.y;  // 32 x 8
    for (int yy = y; yy < 32; yy += 8)
        t[yy][x] = emb[(size_t)(kb + yy) * DIM + db + x];
    __syncthreads();
    for (int yy = y; yy < 32; yy += 8)
        g_eT[(size_t)(db + yy) * NCODES + kb + x] = t[x][yy];
}

// ---------------------------------------------------------------------------
// 2) b_k = sum_d e[k][d]^2
// ---------------------------------------------------------------------------
__global__ void vq_codenorm(const float* __restrict__ emb) {
    int k = blockIdx.x * blockDim.x + threadIdx.x;
    if (k >= NCODES) return;
    const float* row = emb + (size_t)k * DIM;
    float s = 0.0f;
#pragma unroll 8
    for (int d = 0; d < DIM; ++d) s = fmaf(row[d], row[d], s);
    g_b[k] = s;
}

// ---------------------------------------------------------------------------
// 3) main argmin kernel
//    Block: 256 threads, 64 points x 16384 codes (tiles of 256 codes).
//    Register tile: 8 points x 8 codes (4 f32x2 pairs) per thread.
//    smem: es double buffer [d][code] stride 260, zs [d][p] stride 72,
//          sb double buffer, sa.
// ---------------------------------------------------------------------------
#define ES_STRIDE  260
#define ES_FLOATS  (64 * ES_STRIDE)           // 16640
#define ZS_STRIDE  72
#define ZS_FLOATS  (64 * ZS_STRIDE)           // 4608
// layout (floats): es0 | es1 | zs | sb0 | sb1 | sa
#define OFF_ES0    0
#define OFF_ES1    ES_FLOATS
#define OFF_ZS     (2 * ES_FLOATS)
#define OFF_SB0    (OFF_ZS + ZS_FLOATS)
#define OFF_SB1    (OFF_SB0 + 256)
#define OFF_SA     (OFF_SB1 + 256)
#define SM_FLOATS  (OFF_SA + 64)

__global__ __launch_bounds__(256, 1)
void vq_argmin(const float* __restrict__ z, float* __restrict__ out) {
    extern __shared__ float smem[];
    float* zs = smem + OFF_ZS;
    float* sa = smem + OFF_SA;

    const int tid = threadIdx.x;
    const int pg  = tid >> 5;          // warp id = point group (8 pts)
    const int cg  = tid & 31;          // lane = 8 consecutive codes cg*8..cg*8+7

    const int pbase   = blockIdx.x * 64;
    const int bb      = pbase >> 10;
    const int posbase = pbase & 1023;

    // ---- prefetch e tile 0 + b tile 0 (async) ----
    {
        float* es = smem + OFF_ES0;
        for (int c = tid; c < 4096; c += 256) {
            int d = c >> 6, ch = c & 63;
            cp_async16(es + d * ES_STRIDE + ch * 4,
                       g_eT + (size_t)d * NCODES + ch * 4);
        }
        if (tid < 64)
            cp_async16(smem + OFF_SB0 + tid * 4, g_b + tid * 4);
        cp_commit();
    }

    // ---- stage z tile: zs[d][pos] (coalesced both sides) ----
    for (int t = tid; t < 64 * 64; t += 256) {
        int d = t >> 6, pos = t & 63;
        zs[d * ZS_STRIDE + pos] =
            z[(size_t)bb * 65536 + (size_t)d * 1024 + posbase + pos];
    }
    __syncthreads();

    // a_p = sum_d fl(z^2), strictly sequential d = 0..63 (match jnp.sum order)
    if (tid < 64) {
        float s = 0.0f;
        for (int d = 0; d < DIM; ++d) {
            float v = zs[d * ZS_STRIDE + tid];
            s = __fadd_rn(s, __fmul_rn(v, v));
        }
        sa[tid] = s;
    }
    __syncthreads();

    float a_r[8];
#pragma unroll
    for (int i = 0; i < 8; ++i) a_r[i] = sa[pg * 8 + i];

    float bestd[8];
    int   bestk[8];
#pragma unroll
    for (int i = 0; i < 8; ++i) { bestd[i] = __int_as_float(0x7f800000); bestk[i] = 0; }

    const float* zrow = zs + pg * 8;

    for (int tile = 0; tile < NCODES / 256; ++tile) {
        const int cur   = tile & 1;
        const int kbase = tile * 256;

        // prefetch next tile into the other buffer
        if (tile + 1 < NCODES / 256) {
            float* esn = smem + (cur ? OFF_ES0 : OFF_ES1);
            float* sbn = smem + (cur ? OFF_SB0 : OFF_SB1);
            const int kn = kbase + 256;
            for (int c = tid; c < 4096; c += 256) {
                int d = c >> 6, ch = c & 63;
                cp_async16(esn + d * ES_STRIDE + ch * 4,
                           g_eT + (size_t)d * NCODES + kn + ch * 4);
            }
            if (tid < 64)
                cp_async16(sbn + tid * 4, g_b + kn + tid * 4);
        }
        cp_commit();
        cp_wait1();          // current tile's group complete
        __syncthreads();

        const float* es = smem + (cur ? OFF_ES1 : OFF_ES0);
        const float* sb = smem + (cur ? OFF_SB1 : OFF_SB0);

        unsigned long long acc[8][4];
#pragma unroll
        for (int i = 0; i < 8; ++i)
#pragma unroll
            for (int j = 0; j < 4; ++j) acc[i][j] = 0ULL;

#pragma unroll 4
        for (int d = 0; d < DIM; ++d) {
            // z broadcast (LDS.128 x2), duplicate into f32x2
            const float4 za = *(const float4*)(zrow + d * ZS_STRIDE);
            const float4 zb = *(const float4*)(zrow + d * ZS_STRIDE + 4);
            unsigned long long zz[8];
            PACK_DUP(zz[0], za.x); PACK_DUP(zz[1], za.y);
            PACK_DUP(zz[2], za.z); PACK_DUP(zz[3], za.w);
            PACK_DUP(zz[4], zb.x); PACK_DUP(zz[5], zb.y);
            PACK_DUP(zz[6], zb.z); PACK_DUP(zz[7], zb.w);

            // e pairs come packed straight from shared (LDS.64 x4)
            const unsigned long long* ep =
                (const unsigned long long*)(es + d * ES_STRIDE + cg * 8);
            unsigned long long e0 = ep[0], e1 = ep[1], e2 = ep[2], e3 = ep[3];

#pragma unroll
            for (int i = 0; i < 8; ++i) {
                FMA2(acc[i][0], zz[i], e0);
                FMA2(acc[i][1], zz[i], e1);
                FMA2(acc[i][2], zz[i], e2);
                FMA2(acc[i][3], zz[i], e3);
            }
        }

        // epilogue: dist = fl( fl(a+b) - 2c ); strict < keeps smallest index
        // (k ascends with jp and lo/hi within thread)
#pragma unroll
        for (int jp = 0; jp < 4; ++jp) {
            const int klo = kbase + cg * 8 + 2 * jp;
            const float blo = sb[cg * 8 + 2 * jp];
            const float bhi = sb[cg * 8 + 2 * jp + 1];
#pragma unroll
            for (int i = 0; i < 8; ++i) {
                float clo, chi;
                UNPACK2(clo, chi, acc[i][jp]);
                float dlo = fmaf(-2.0f, clo, __fadd_rn(a_r[i], blo));
                float dhi = fmaf(-2.0f, chi, __fadd_rn(a_r[i], bhi));
                if (dlo < bestd[i]) { bestd[i] = dlo; bestk[i] = klo; }
                if (dhi < bestd[i]) { bestd[i] = dhi; bestk[i] = klo + 1; }
            }
        }
        __syncthreads();   // before next prefetch overwrites the buffer we read
    }

    // cross-lane reduction: lanes cg ascending == code ascending, strict <
    float* rd = smem;                       // 2048 floats
    int*   ri = (int*)(smem + 2048);        // 2048 ints
#pragma unroll
    for (int i = 0; i < 8; ++i) {
        rd[tid * 8 + i] = bestd[i];
        ri[tid * 8 + i] = bestk[i];
    }
    __syncthreads();

    if (tid < 64) {
        int p  = tid;
        int mg = p >> 3;
        int mi = p & 7;
        float bd = __int_as_float(0x7f800000);
        int   bk = 0x7fffffff;
        for (int c = 0; c < 32; ++c) {
            int   t2 = (mg * 32 + c) * 8 + mi;
            float d2 = rd[t2];
            int   k2 = ri[t2];
            if (d2 < bd || (d2 == bd && k2 < bk)) { bd = d2; bk = k2; }
        }
        g_idx[pbase + p] = bk;
        out[OFF_IDX + pbase + p] = (float)bk;
        out[OFF_USAGE + bk] = 1.0f;          // idempotent usage scatter
    }
}

// ---------------------------------------------------------------------------
// 4) z_q gather + loss accumulation (256 blocks, grid-stride x8)
// ---------------------------------------------------------------------------
__global__ void vq_zq_loss(const float* __restrict__ z,
                           const float* __restrict__ emb,
                           float* __restrict__ out) {
    __shared__ double sd[256];
    double acc = 0.0;
    for (int g = blockIdx.x * 256 + threadIdx.x; g < 524288; g += 65536) {
        int d   = (g >> 10) & 63;
        int bb  = g >> 16;
        int pos = g & 1023;
        int k   = g_idx[bb * 1024 + pos];
        float e  = emb[(size_t)k * DIM + d];
        float zv = z[g];
        out[OFF_ZQ + g] = e;
        float diff = e - zv;
        acc += (double)diff * (double)diff;
    }
    sd[threadIdx.x] = acc;
    __syncthreads();
    for (int s = 128; s > 0; s >>= 1) {
        if (threadIdx.x < s) sd[threadIdx.x] += sd[threadIdx.x + s];
        __syncthreads();
    }
    if (threadIdx.x == 0) atomicAdd(&g_loss, sd[0]);
}

// ---------------------------------------------------------------------------
// 5) finalize: num_unique, total_usage, loss
// ---------------------------------------------------------------------------
__global__ void vq_finalize(float* out) {
    __shared__ float sf[512];
    float s = 0.0f;
    for (int t = threadIdx.x; t < NCODES; t += 512) s += out[OFF_USAGE + t];
    sf[threadIdx.x] = s;
    __syncthreads();
    for (int st = 256; st > 0; st >>= 1) {
        if (threadIdx.x < st) sf[threadIdx.x] += sf[threadIdx.x + st];
        __syncthreads();
    }
    if (threadIdx.x == 0) {
        float total = sf[0];
        out[OFF_NUNIQ] = total;
        out[OFF_TOTAL] = total / (float)NCODES;
        float m = (float)(g_loss / 524288.0);
        out[OFF_LOSS] = m + 0.25f * m;
    }
}

// ---------------------------------------------------------------------------
extern "C" void kernel_launch(void* const* d_in, const int* in_sizes, int n_in,
                              void* d_out, int out_size) {
    const float* z;
    const float* emb;
    if (in_sizes[0] == 524288) {
        z = (const float*)d_in[0];
        emb = (const float*)d_in[1];
    } else {
        z = (const float*)d_in[1];
        emb = (const float*)d_in[0];
    }
    float* out = (float*)d_out;

    static int attr_set = 0;
    if (!attr_set) {
        cudaFuncSetAttribute(vq_argmin, cudaFuncAttributeMaxDynamicSharedMemorySize,
                             SM_FLOATS * (int)sizeof(float));
        attr_set = 1;
    }

    vq_init<<<(NCODES + 255) / 256, 256>>>(out);
    vq_transpose<<<dim3(NCODES / 32, DIM / 32), dim3(32, 8)>>>(emb);
    vq_codenorm<<<(NCODES + 255) / 256, 256>>>(emb);
    vq_argmin<<<NPTS / 64, 256, SM_FLOATS * sizeof(float)>>>(z, out);
    vq_zq_loss<<<256, 256>>>(z, emb, out);
    vq_finalize<<<1, 512>>>(out);
}